// round 11
// baseline (speedup 1.0000x reference)
#include <cuda_runtime.h>
#include <cuda_bf16.h>
#include <math.h>

#define B_SZ 256
#define L_SZ 16384
#define NCHUNK 4
#define CS (L_SZ / NCHUNK)          // 4096 positions per chunk, 4 iters/thread
#define NPART 10                    // 6 mat entries + 3 counts + ce

// Scratch: g_part[(c*NPART + i) * B_SZ + b]  (lane-coalesced over b)
__device__ float g_part[NCHUNK * NPART * B_SZ];

__device__ __forceinline__ float frcp(float x) {
    float r;
    asm("rcp.approx.f32 %0, %1;" : "=f"(r) : "f"(x));
    return r;
}

// One token, direct rcp. Returns s4v (=1 for invalid) for the batched log.
__device__ __forceinline__ float tok1(
    float x0, float x1, float x2, float x3, int lab,
    float acc[6], unsigned& npack, float& ce)
{
    float e0 = __expf(x0), e1 = __expf(x1), e2 = __expf(x2), e3 = __expf(x3);
    float s3 = (e0 + e1) + e2;
    bool  valid = (lab != 3);
    float s4v = valid ? (s3 + e3) : 1.0f;
    float xl = (lab == 0) ? x0 : (lab == 1) ? x1 : x2;
    if (valid) ce -= xl;

    float q  = frcp(s3);
    float p0 = e0 * q, p1 = e1 * q;
    if (lab == 0)      { acc[0] += p0; acc[1] += p1; npack += 1u; }
    else if (lab == 1) { acc[2] += p0; acc[3] += p1; npack += (1u << 10); }
    else if (lab == 2) { acc[4] += p0; acc[5] += p1; npack += (1u << 20); }
    return s4v;
}

__global__ __launch_bounds__(256, 5) void k2_main(
    const float* __restrict__ pred, const int* __restrict__ labels)
{
    const int tid = threadIdx.x;
    const int ch = blockIdx.x;
    const int b  = blockIdx.y;

    const float* P  = pred + (size_t)b * 4 * L_SZ + ch * CS;
    const int*   Lb = labels + (size_t)b * L_SZ + ch * CS;

    float acc[6];
#pragma unroll
    for (int i = 0; i < 6; ++i) acc[i] = 0.0f;
    unsigned npack = 0u;
    float ce = 0.0f;

#pragma unroll
    for (int it = 0; it < 4; ++it) {
        const int l = it * 1024 + tid * 4;
        // Issue ALL loads unconditionally and in parallel (MLP=5): the ballot
        // gates only COMPUTE, never the memory stream. Pads cost bandwidth
        // only, and bandwidth has 3x headroom.
        int4   lb = *reinterpret_cast<const int4*>(Lb + l);
        float4 a0 = *reinterpret_cast<const float4*>(P + l);
        float4 a1 = *reinterpret_cast<const float4*>(P + L_SZ + l);
        float4 a2 = *reinterpret_cast<const float4*>(P + 2 * L_SZ + l);
        float4 a3 = *reinterpret_cast<const float4*>(P + 3 * L_SZ + l);

        bool any_valid = (lb.x != 3) | (lb.y != 3) | (lb.z != 3) | (lb.w != 3);
        if (__ballot_sync(0xFFFFFFFFu, any_valid) != 0u) {
            float sx = tok1(a0.x, a1.x, a2.x, a3.x, lb.x, acc, npack, ce);
            float sy = tok1(a0.y, a1.y, a2.y, a3.y, lb.y, acc, npack, ce);
            float sz = tok1(a0.z, a1.z, a2.z, a3.z, lb.z, acc, npack, ce);
            float sw = tok1(a0.w, a1.w, a2.w, a3.w, lb.w, acc, npack, ce);
            ce += __logf((sx * sy) * (sz * sw));
        }
    }

    // Warp reduction: 7 floats + 1 packed int.
#pragma unroll
    for (int off = 16; off > 0; off >>= 1) {
#pragma unroll
        for (int i = 0; i < 6; ++i)
            acc[i] += __shfl_xor_sync(0xFFFFFFFFu, acc[i], off);
        ce    += __shfl_xor_sync(0xFFFFFFFFu, ce, off);
        npack += __shfl_xor_sync(0xFFFFFFFFu, npack, off);
    }

    __shared__ float sm[8][NPART];
    const int wid = tid >> 5, lane = tid & 31;
    if (lane == 0) {
#pragma unroll
        for (int i = 0; i < 6; ++i) sm[wid][i] = acc[i];
        sm[wid][6] = (float)(npack & 1023u);
        sm[wid][7] = (float)((npack >> 10) & 1023u);
        sm[wid][8] = (float)((npack >> 20) & 1023u);
        sm[wid][9] = ce;
    }
    __syncthreads();
    if (tid == 0) {
#pragma unroll
        for (int i = 0; i < NPART; ++i) {
            float s = 0.0f;
#pragma unroll
            for (int w = 0; w < 8; ++w) s += sm[w][i];
            g_part[(ch * NPART + i) * B_SZ + b] = s;
        }
    }
}

// ---------------- K3: finalize (cheap in wall time; ncu inflates it) -------
__global__ __launch_bounds__(1024) void k3_final(float* __restrict__ out) {
    if (blockIdx.x != 0) return;

    const int tid = threadIdx.x;
    const int g   = tid >> 8;       // 0..3 -> one chunk each
    const int b   = tid & 255;      // row

    // Batched prefetch: 10 independent loads, no consumer in between.
    float v[NPART];
#pragma unroll
    for (int i = 0; i < NPART; ++i)
        v[i] = g_part[(g * NPART + i) * B_SZ + b];

    __shared__ float smg[4][NPART][B_SZ];    // 40KB, b lane-major: conflict-free
#pragma unroll
    for (int i = 0; i < NPART; ++i)
        smg[g][i][b] = v[i];
    __syncthreads();

    __shared__ double s_dmi[B_SZ];
    __shared__ double s_ce[B_SZ];
    __shared__ double s_cnt[B_SZ];

    if (g == 0) {
        float m[NPART];
#pragma unroll
        for (int i = 0; i < NPART; ++i)
            m[i] = (smg[0][i][b] + smg[1][i][b]) + (smg[2][i][b] + smg[3][i][b]);

        float n0 = m[6], n1 = m[7], n2 = m[8], ce = m[9];
        float cnt = n0 + n1 + n2;   // == j (pads are a suffix, always present)

        // 3x3 rows (raw sums); col2 from row counts; det(M/j)=det(M)/j^3
        double a0 = m[0], a1 = m[1], a2 = (double)n0 - m[0] - m[1];
        double b0 = m[2], b1 = m[3], b2 = (double)n1 - m[2] - m[3];
        double c0 = m[4], c1 = m[5], c2 = (double)n2 - m[4] - m[5];

        double det = a0 * (b1 * c2 - b2 * c1)
                   - a1 * (b0 * c2 - b2 * c0)
                   + a2 * (b0 * c1 - b1 * c0);
        double jf = (double)cnt;
        double dets = det / (jf * jf * jf);

        float arg = (float)fabs(dets) + 1e-3f;
        float lg = __logf(arg);
        float dmi = (dets < 0.0) ? lg : -lg;

        s_dmi[b] = (double)dmi;
        s_ce[b]  = (double)ce;
        s_cnt[b] = (double)cnt;
    }
    __syncthreads();

    for (int s = 128; s > 0; s >>= 1) {
        if (tid < s) {
            s_dmi[tid] += s_dmi[tid + s];
            s_ce[tid]  += s_ce[tid + s];
            s_cnt[tid] += s_cnt[tid + s];
        }
        __syncthreads();
    }
    if (tid == 0) {
        double loss = 0.1 * (s_dmi[0] / (double)B_SZ) + s_ce[0] / s_cnt[0];
        out[0] = (float)loss;
    }
}

extern "C" void kernel_launch(void* const* d_in, const int* in_sizes, int n_in,
                              void* d_out, int out_size) {
    const float* pred;
    const int*   labels;
    if (in_sizes[0] == B_SZ * 4 * L_SZ) {
        pred   = (const float*)d_in[0];
        labels = (const int*)d_in[1];
    } else {
        pred   = (const float*)d_in[1];
        labels = (const int*)d_in[0];
    }
    float* out = (float*)d_out;

    dim3 g2(NCHUNK, B_SZ);
    k2_main<<<g2, 256>>>(pred, labels);
    k3_final<<<160, 1024>>>(out);
}

// round 12
// speedup vs baseline: 1.0476x; 1.0476x over previous
#include <cuda_runtime.h>
#include <cuda_bf16.h>
#include <math.h>

#define B_SZ 256
#define L_SZ 16384
#define NCHUNK 4
#define CS (L_SZ / NCHUNK)          // 4096 positions per chunk, 4 iters/thread
#define NPART 10                    // 6 mat entries + 3 counts + ce

// Scratch: g_part[(c*NPART + i) * B_SZ + b]  (lane-coalesced over b)
__device__ float g_part[NCHUNK * NPART * B_SZ];

__device__ __forceinline__ float frcp(float x) {
    float r;
    asm("rcp.approx.f32 %0, %1;" : "=f"(r) : "f"(x));
    return r;
}

// One token, direct rcp. Returns s4v (=1 for invalid) for the batched log.
__device__ __forceinline__ float tok1(
    float x0, float x1, float x2, float x3, int lab,
    float acc[6], unsigned& npack, float& ce)
{
    float e0 = __expf(x0), e1 = __expf(x1), e2 = __expf(x2), e3 = __expf(x3);
    float s3 = (e0 + e1) + e2;
    bool  valid = (lab != 3);
    float s4v = valid ? (s3 + e3) : 1.0f;
    float xl = (lab == 0) ? x0 : (lab == 1) ? x1 : x2;
    if (valid) ce -= xl;

    float q  = frcp(s3);
    float p0 = e0 * q, p1 = e1 * q;
    if (lab == 0)      { acc[0] += p0; acc[1] += p1; npack += 1u; }
    else if (lab == 1) { acc[2] += p0; acc[3] += p1; npack += (1u << 10); }
    else if (lab == 2) { acc[4] += p0; acc[5] += p1; npack += (1u << 20); }
    return s4v;
}

__device__ __forceinline__ void do_iter4(
    const float4& a0, const float4& a1, const float4& a2, const float4& a3,
    const int4& lb, float acc[6], unsigned& npack, float& ce)
{
    float sx = tok1(a0.x, a1.x, a2.x, a3.x, lb.x, acc, npack, ce);
    float sy = tok1(a0.y, a1.y, a2.y, a3.y, lb.y, acc, npack, ce);
    float sz = tok1(a0.z, a1.z, a2.z, a3.z, lb.z, acc, npack, ce);
    float sw = tok1(a0.w, a1.w, a2.w, a3.w, lb.w, acc, npack, ce);
    ce += __logf((sx * sy) * (sz * sw));
}

__global__ __launch_bounds__(256, 4) void k2_main(
    const float* __restrict__ pred, const int* __restrict__ labels)
{
    const int tid = threadIdx.x;
    const int ch = blockIdx.x;
    const int b  = blockIdx.y;

    const float* P  = pred + (size_t)b * 4 * L_SZ + ch * CS;
    const int*   Lb = labels + (size_t)b * L_SZ + ch * CS;

    float acc[6];
#pragma unroll
    for (int i = 0; i < 6; ++i) acc[i] = 0.0f;
    unsigned npack = 0u;
    float ce = 0.0f;

    // Front-batch ALL four iterations' labels: 4 independent coalesced int4
    // loads (one exposed round-trip), then all ballots.
    const int l0 = tid * 4;
    int4 lb0 = *reinterpret_cast<const int4*>(Lb + l0);
    int4 lb1 = *reinterpret_cast<const int4*>(Lb + 1024 + l0);
    int4 lb2 = *reinterpret_cast<const int4*>(Lb + 2048 + l0);
    int4 lb3 = *reinterpret_cast<const int4*>(Lb + 3072 + l0);
    bool av0 = (lb0.x != 3) | (lb0.y != 3) | (lb0.z != 3) | (lb0.w != 3);
    bool av1 = (lb1.x != 3) | (lb1.y != 3) | (lb1.z != 3) | (lb1.w != 3);
    bool av2 = (lb2.x != 3) | (lb2.y != 3) | (lb2.z != 3) | (lb2.w != 3);
    bool av3 = (lb3.x != 3) | (lb3.y != 3) | (lb3.z != 3) | (lb3.w != 3);
    unsigned bal0 = __ballot_sync(0xFFFFFFFFu, av0);
    unsigned bal1 = __ballot_sync(0xFFFFFFFFu, av1);
    unsigned bal2 = __ballot_sync(0xFFFFFFFFu, av2);
    unsigned bal3 = __ballot_sync(0xFFFFFFFFu, av3);

    // Group {0,1}: issue both iterations' pred loads (MLP=8), then compute.
    {
        float4 b00, b01, b02, b03, b10, b11, b12, b13;
        if (bal0) {
            b00 = *reinterpret_cast<const float4*>(P + l0);
            b01 = *reinterpret_cast<const float4*>(P + L_SZ + l0);
            b02 = *reinterpret_cast<const float4*>(P + 2 * L_SZ + l0);
            b03 = *reinterpret_cast<const float4*>(P + 3 * L_SZ + l0);
        }
        if (bal1) {
            const int l = 1024 + l0;
            b10 = *reinterpret_cast<const float4*>(P + l);
            b11 = *reinterpret_cast<const float4*>(P + L_SZ + l);
            b12 = *reinterpret_cast<const float4*>(P + 2 * L_SZ + l);
            b13 = *reinterpret_cast<const float4*>(P + 3 * L_SZ + l);
        }
        if (bal0) do_iter4(b00, b01, b02, b03, lb0, acc, npack, ce);
        if (bal1) do_iter4(b10, b11, b12, b13, lb1, acc, npack, ce);
    }

    // Group {2,3}
    {
        float4 b00, b01, b02, b03, b10, b11, b12, b13;
        if (bal2) {
            const int l = 2048 + l0;
            b00 = *reinterpret_cast<const float4*>(P + l);
            b01 = *reinterpret_cast<const float4*>(P + L_SZ + l);
            b02 = *reinterpret_cast<const float4*>(P + 2 * L_SZ + l);
            b03 = *reinterpret_cast<const float4*>(P + 3 * L_SZ + l);
        }
        if (bal3) {
            const int l = 3072 + l0;
            b10 = *reinterpret_cast<const float4*>(P + l);
            b11 = *reinterpret_cast<const float4*>(P + L_SZ + l);
            b12 = *reinterpret_cast<const float4*>(P + 2 * L_SZ + l);
            b13 = *reinterpret_cast<const float4*>(P + 3 * L_SZ + l);
        }
        if (bal2) do_iter4(b00, b01, b02, b03, lb2, acc, npack, ce);
        if (bal3) do_iter4(b10, b11, b12, b13, lb3, acc, npack, ce);
    }

    // Warp reduction: 7 floats + 1 packed int.
#pragma unroll
    for (int off = 16; off > 0; off >>= 1) {
#pragma unroll
        for (int i = 0; i < 6; ++i)
            acc[i] += __shfl_xor_sync(0xFFFFFFFFu, acc[i], off);
        ce    += __shfl_xor_sync(0xFFFFFFFFu, ce, off);
        npack += __shfl_xor_sync(0xFFFFFFFFu, npack, off);
    }

    __shared__ float sm[8][NPART];
    const int wid = tid >> 5, lane = tid & 31;
    if (lane == 0) {
#pragma unroll
        for (int i = 0; i < 6; ++i) sm[wid][i] = acc[i];
        sm[wid][6] = (float)(npack & 1023u);
        sm[wid][7] = (float)((npack >> 10) & 1023u);
        sm[wid][8] = (float)((npack >> 20) & 1023u);
        sm[wid][9] = ce;
    }
    __syncthreads();
    if (tid == 0) {
#pragma unroll
        for (int i = 0; i < NPART; ++i) {
            float s = 0.0f;
#pragma unroll
            for (int w = 0; w < 8; ++w) s += sm[w][i];
            g_part[(ch * NPART + i) * B_SZ + b] = s;
        }
    }
}

// ---------------- K3: finalize ----------------
__global__ __launch_bounds__(1024) void k3_final(float* __restrict__ out) {
    if (blockIdx.x != 0) return;

    const int tid = threadIdx.x;
    const int g   = tid >> 8;       // 0..3 -> one chunk each
    const int b   = tid & 255;      // row

    float v[NPART];
#pragma unroll
    for (int i = 0; i < NPART; ++i)
        v[i] = g_part[(g * NPART + i) * B_SZ + b];

    __shared__ float smg[4][NPART][B_SZ];    // 40KB, b lane-major: conflict-free
#pragma unroll
    for (int i = 0; i < NPART; ++i)
        smg[g][i][b] = v[i];
    __syncthreads();

    __shared__ double s_dmi[B_SZ];
    __shared__ double s_ce[B_SZ];
    __shared__ double s_cnt[B_SZ];

    if (g == 0) {
        float m[NPART];
#pragma unroll
        for (int i = 0; i < NPART; ++i)
            m[i] = (smg[0][i][b] + smg[1][i][b]) + (smg[2][i][b] + smg[3][i][b]);

        float n0 = m[6], n1 = m[7], n2 = m[8], ce = m[9];
        float cnt = n0 + n1 + n2;   // == j (pads are a suffix, always present)

        double a0 = m[0], a1 = m[1], a2 = (double)n0 - m[0] - m[1];
        double b0 = m[2], b1 = m[3], b2 = (double)n1 - m[2] - m[3];
        double c0 = m[4], c1 = m[5], c2 = (double)n2 - m[4] - m[5];

        double det = a0 * (b1 * c2 - b2 * c1)
                   - a1 * (b0 * c2 - b2 * c0)
                   + a2 * (b0 * c1 - b1 * c0);
        double jf = (double)cnt;
        double dets = det / (jf * jf * jf);

        float arg = (float)fabs(dets) + 1e-3f;
        float lg = __logf(arg);
        float dmi = (dets < 0.0) ? lg : -lg;

        s_dmi[b] = (double)dmi;
        s_ce[b]  = (double)ce;
        s_cnt[b] = (double)cnt;
    }
    __syncthreads();

    for (int s = 128; s > 0; s >>= 1) {
        if (tid < s) {
            s_dmi[tid] += s_dmi[tid + s];
            s_ce[tid]  += s_ce[tid + s];
            s_cnt[tid] += s_cnt[tid + s];
        }
        __syncthreads();
    }
    if (tid == 0) {
        double loss = 0.1 * (s_dmi[0] / (double)B_SZ) + s_ce[0] / s_cnt[0];
        out[0] = (float)loss;
    }
}

extern "C" void kernel_launch(void* const* d_in, const int* in_sizes, int n_in,
                              void* d_out, int out_size) {
    const float* pred;
    const int*   labels;
    if (in_sizes[0] == B_SZ * 4 * L_SZ) {
        pred   = (const float*)d_in[0];
        labels = (const int*)d_in[1];
    } else {
        pred   = (const float*)d_in[1];
        labels = (const int*)d_in[0];
    }
    float* out = (float*)d_out;

    dim3 g2(NCHUNK, B_SZ);
    k2_main<<<g2, 256>>>(pred, labels);
    k3_final<<<160, 1024>>>(out);
}

// round 13
// speedup vs baseline: 1.0708x; 1.0222x over previous
#include <cuda_runtime.h>
#include <cuda_bf16.h>
#include <math.h>

#define B_SZ 256
#define L_SZ 16384
#define NCHUNK 4
#define CS (L_SZ / NCHUNK)          // 4096 positions per chunk, 4 iters/thread
#define NPART 10                    // 6 mat entries + 3 counts + ce

// Scratch: g_part[(c*NPART + i) * B_SZ + b]  (lane-coalesced over b)
__device__ float g_part[NCHUNK * NPART * B_SZ];

__device__ __forceinline__ float frcp(float x) {
    float r;
    asm("rcp.approx.f32 %0, %1;" : "=f"(r) : "f"(x));
    return r;
}

// One token, direct rcp. Returns s4v (=1 for invalid) for the batched log.
__device__ __forceinline__ float tok1(
    float x0, float x1, float x2, float x3, int lab,
    float acc[6], unsigned& npack, float& ce)
{
    float e0 = __expf(x0), e1 = __expf(x1), e2 = __expf(x2), e3 = __expf(x3);
    float s3 = (e0 + e1) + e2;
    bool  valid = (lab != 3);
    float s4v = valid ? (s3 + e3) : 1.0f;
    float xl = (lab == 0) ? x0 : (lab == 1) ? x1 : x2;
    if (valid) ce -= xl;

    float q  = frcp(s3);
    float p0 = e0 * q, p1 = e1 * q;
    if (lab == 0)      { acc[0] += p0; acc[1] += p1; npack += 1u; }
    else if (lab == 1) { acc[2] += p0; acc[3] += p1; npack += (1u << 10); }
    else if (lab == 2) { acc[4] += p0; acc[5] += p1; npack += (1u << 20); }
    return s4v;
}

__device__ __forceinline__ void do_iter4(
    const float4& a0, const float4& a1, const float4& a2, const float4& a3,
    const int4& lb, float acc[6], unsigned& npack, float& ce)
{
    float sx = tok1(a0.x, a1.x, a2.x, a3.x, lb.x, acc, npack, ce);
    float sy = tok1(a0.y, a1.y, a2.y, a3.y, lb.y, acc, npack, ce);
    float sz = tok1(a0.z, a1.z, a2.z, a3.z, lb.z, acc, npack, ce);
    float sw = tok1(a0.w, a1.w, a2.w, a3.w, lb.w, acc, npack, ce);
    ce += __logf((sx * sy) * (sz * sw));
}

__global__ __launch_bounds__(256, 4) void k2_main(
    const float* __restrict__ pred, const int* __restrict__ labels)
{
    const int tid = threadIdx.x;
    const int ch = blockIdx.x;
    const int b  = blockIdx.y;

    const float* P  = pred + (size_t)b * 4 * L_SZ + ch * CS;
    const int*   Lb = labels + (size_t)b * L_SZ + ch * CS;

    float acc[6];
#pragma unroll
    for (int i = 0; i < 6; ++i) acc[i] = 0.0f;
    unsigned npack = 0u;
    float ce = 0.0f;

    // Front-batch ALL four iterations' labels (one exposed round-trip).
    const int l0 = tid * 4;
    int4 lbs[4];
    lbs[0] = *reinterpret_cast<const int4*>(Lb + l0);
    lbs[1] = *reinterpret_cast<const int4*>(Lb + 1024 + l0);
    lbs[2] = *reinterpret_cast<const int4*>(Lb + 2048 + l0);
    lbs[3] = *reinterpret_cast<const int4*>(Lb + 3072 + l0);
    unsigned bal[4];
#pragma unroll
    for (int i = 0; i < 4; ++i) {
        bool av = (lbs[i].x != 3) | (lbs[i].y != 3) | (lbs[i].z != 3) | (lbs[i].w != 3);
        bal[i] = __ballot_sync(0xFFFFFFFFu, av);
    }

    // Software pipeline, 1-deep prefetch: compute(it) always overlaps
    // load(it+1) -> a warp has loads in flight during every compute phase.
    float4 c0, c1, c2, c3;      // current iteration's data
    if (bal[0]) {
        c0 = *reinterpret_cast<const float4*>(P + l0);
        c1 = *reinterpret_cast<const float4*>(P + L_SZ + l0);
        c2 = *reinterpret_cast<const float4*>(P + 2 * L_SZ + l0);
        c3 = *reinterpret_cast<const float4*>(P + 3 * L_SZ + l0);
    }
#pragma unroll
    for (int it = 0; it < 4; ++it) {
        float4 n0, n1, n2, n3;
        if (it < 3 && bal[it + 1]) {
            const int l = (it + 1) * 1024 + l0;
            n0 = *reinterpret_cast<const float4*>(P + l);
            n1 = *reinterpret_cast<const float4*>(P + L_SZ + l);
            n2 = *reinterpret_cast<const float4*>(P + 2 * L_SZ + l);
            n3 = *reinterpret_cast<const float4*>(P + 3 * L_SZ + l);
        }
        if (bal[it])
            do_iter4(c0, c1, c2, c3, lbs[it], acc, npack, ce);
        c0 = n0; c1 = n1; c2 = n2; c3 = n3;
    }

    // Warp reduction: 7 floats + 1 packed int.
#pragma unroll
    for (int off = 16; off > 0; off >>= 1) {
#pragma unroll
        for (int i = 0; i < 6; ++i)
            acc[i] += __shfl_xor_sync(0xFFFFFFFFu, acc[i], off);
        ce    += __shfl_xor_sync(0xFFFFFFFFu, ce, off);
        npack += __shfl_xor_sync(0xFFFFFFFFu, npack, off);
    }

    __shared__ float sm[8][NPART];
    const int wid = tid >> 5, lane = tid & 31;
    if (lane == 0) {
#pragma unroll
        for (int i = 0; i < 6; ++i) sm[wid][i] = acc[i];
        sm[wid][6] = (float)(npack & 1023u);
        sm[wid][7] = (float)((npack >> 10) & 1023u);
        sm[wid][8] = (float)((npack >> 20) & 1023u);
        sm[wid][9] = ce;
    }
    __syncthreads();
    if (tid == 0) {
#pragma unroll
        for (int i = 0; i < NPART; ++i) {
            float s = 0.0f;
#pragma unroll
            for (int w = 0; w < 8; ++w) s += sm[w][i];
            g_part[(ch * NPART + i) * B_SZ + b] = s;
        }
    }
}

// ---------------- K3: finalize ----------------
__global__ __launch_bounds__(1024) void k3_final(float* __restrict__ out) {
    if (blockIdx.x != 0) return;

    const int tid = threadIdx.x;
    const int g   = tid >> 8;       // 0..3 -> one chunk each
    const int b   = tid & 255;      // row

    float v[NPART];
#pragma unroll
    for (int i = 0; i < NPART; ++i)
        v[i] = g_part[(g * NPART + i) * B_SZ + b];

    __shared__ float smg[4][NPART][B_SZ];    // 40KB, b lane-major: conflict-free
#pragma unroll
    for (int i = 0; i < NPART; ++i)
        smg[g][i][b] = v[i];
    __syncthreads();

    __shared__ double s_dmi[B_SZ];
    __shared__ double s_ce[B_SZ];
    __shared__ double s_cnt[B_SZ];

    if (g == 0) {
        float m[NPART];
#pragma unroll
        for (int i = 0; i < NPART; ++i)
            m[i] = (smg[0][i][b] + smg[1][i][b]) + (smg[2][i][b] + smg[3][i][b]);

        float n0 = m[6], n1 = m[7], n2 = m[8], ce = m[9];
        float cnt = n0 + n1 + n2;   // == j (pads are a suffix, always present)

        double a0 = m[0], a1 = m[1], a2 = (double)n0 - m[0] - m[1];
        double b0 = m[2], b1 = m[3], b2 = (double)n1 - m[2] - m[3];
        double c0 = m[4], c1 = m[5], c2 = (double)n2 - m[4] - m[5];

        double det = a0 * (b1 * c2 - b2 * c1)
                   - a1 * (b0 * c2 - b2 * c0)
                   + a2 * (b0 * c1 - b1 * c0);
        double jf = (double)cnt;
        double dets = det / (jf * jf * jf);

        float arg = (float)fabs(dets) + 1e-3f;
        float lg = __logf(arg);
        float dmi = (dets < 0.0) ? lg : -lg;

        s_dmi[b] = (double)dmi;
        s_ce[b]  = (double)ce;
        s_cnt[b] = (double)cnt;
    }
    __syncthreads();

    for (int s = 128; s > 0; s >>= 1) {
        if (tid < s) {
            s_dmi[tid] += s_dmi[tid + s];
            s_ce[tid]  += s_ce[tid + s];
            s_cnt[tid] += s_cnt[tid + s];
        }
        __syncthreads();
    }
    if (tid == 0) {
        double loss = 0.1 * (s_dmi[0] / (double)B_SZ) + s_ce[0] / s_cnt[0];
        out[0] = (float)loss;
    }
}

extern "C" void kernel_launch(void* const* d_in, const int* in_sizes, int n_in,
                              void* d_out, int out_size) {
    const float* pred;
    const int*   labels;
    if (in_sizes[0] == B_SZ * 4 * L_SZ) {
        pred   = (const float*)d_in[0];
        labels = (const int*)d_in[1];
    } else {
        pred   = (const float*)d_in[1];
        labels = (const int*)d_in[0];
    }
    float* out = (float*)d_out;

    dim3 g2(NCHUNK, B_SZ);
    k2_main<<<g2, 256>>>(pred, labels);
    k3_final<<<160, 1024>>>(out);
}